// round 17
// baseline (speedup 1.0000x reference)
#include <cuda_runtime.h>
#include <cuda_fp16.h>
#include <math.h>
#include <stdint.h>

#define BATCH 16
#define CCH   2048
#define HWD   1024
#define DD    256
#define BN_RS 0.9999950000374997f   // 1/sqrt(1 + 1e-5)

// ---------------- scratch (device globals; no allocation) ----------------
__device__ __align__(16) float d_G  [BATCH * DD * DD];
__device__ float d_invr[BATCH * DD];

__device__ __align__(16) __half g_v2lh[BATCH*CCH*HWD];
__device__ __align__(16) __half g_l2vh[BATCH*CCH*HWD];
__device__ __align__(16) __half g_wvh[DD*HWD];
__device__ __align__(16) __half g_wlh[DD*HWD];
__device__ __align__(16) __half g_Yvh[BATCH*DD*CCH];
__device__ __align__(16) __half g_Zlh[BATCH*CCH*DD];
__device__ __align__(16) __half g_Eh[BATCH*DD*HWD];
__device__ __align__(16) __half g_Oh[BATCH*DD*HWD];
__device__ __align__(16) __half g_Zh[BATCH*CCH*DD];
__device__ __align__(16) __half g_lath[BATCH*DD*HWD];
__device__ __align__(16) __half g_latTh[BATCH*HWD*DD];
__device__ __align__(16) __half g_Gh[BATCH*DD*DD];
__device__ __align__(16) __half g_l2Th[BATCH*HWD*DD];

// ---------------- helpers ----------------
__device__ __forceinline__ uint32_t cvta_s(const void* p){
    return (uint32_t)__cvta_generic_to_shared(p);
}
__device__ __forceinline__ void cpa16(uint32_t d, const void* s){
    asm volatile("cp.async.cg.shared.global [%0], [%1], 16;" :: "r"(d), "l"(s));
}
#define CP_COMMIT() asm volatile("cp.async.commit_group;")
#define CP_WAIT1()  asm volatile("cp.async.wait_group 1;")

#define LDSM4(R, addr) \
    asm volatile("ldmatrix.sync.aligned.m8n8.x4.shared.b16 {%0,%1,%2,%3}, [%4];" \
        : "=r"((R)[0]), "=r"((R)[1]), "=r"((R)[2]), "=r"((R)[3]) : "r"(addr))

#define MMA16816(d, A, b0, b1) \
    asm volatile("mma.sync.aligned.m16n8k16.row.col.f32.f16.f16.f32 " \
        "{%0,%1,%2,%3}, {%4,%5,%6,%7}, {%8,%9}, {%0,%1,%2,%3};" \
        : "+f"((d)[0]), "+f"((d)[1]), "+f"((d)[2]), "+f"((d)[3]) \
        : "r"((A)[0]), "r"((A)[1]), "r"((A)[2]), "r"((A)[3]), "r"(b0), "r"(b1))

__device__ __forceinline__ uint32_t packh(float x, float y){
    __half2 h = __floats2half2_rn(x, y);
    return *(uint32_t*)&h;
}
__device__ __forceinline__ void split16h(float4 v, uint2& hi){
    hi.x = packh(v.x, v.y); hi.y = packh(v.z, v.w);
}

// ---------------- fp16 NT GEMM core (64-K stages, 3-ring, 2 CTA/SM) -------
struct GArgs {
    const __half *A0, *B0, *A1, *B1;
    void *C;
    const float *gs, *bs;
    long sA, sB, sC;
    int lda, ldb, ldc, K;
};
struct GPair { GArgs g0, g1; };

#define STG64  32768
#define G_SMEM (3 * STG64)

// mainloop shared by all GEMM kernels (device-inlined)
template<int NP>
__device__ __forceinline__ void gemm_main(
    const GArgs& a, char* smem, int bn0, int bm0, int b, float acc[4][4][4])
{
    const int tid = threadIdx.x, lane = tid & 31;
    const int w = tid >> 5;
    const int wm = w >> 2, wn = w & 3;
    const int KS = a.K >> 6;
    const int NS = KS * NP;
    const uint32_t sbase = cvta_s(smem);

    const int r0 = tid >> 2, ch = tid & 3;
    const uint32_t q16 = (uint32_t)((ch ^ ((r0 >> 1) & 3)) * 16);

    auto issue = [&](int s){
        if (s >= NS) return;
        int p = (NP == 2 && s >= KS) ? 1 : 0;
        long kbase = (long)(s - p * KS) * 64;
        const __half* Ab = (p ? a.A1 : a.A0) + (long)b * a.sA + (long)bm0 * a.lda;
        const __half* Bb = (p ? a.B1 : a.B0) + (long)b * a.sB + (long)bn0 * a.ldb;
        uint32_t dst0 = sbase + (uint32_t)(s % 3) * STG64 + (uint32_t)r0 * 64u + q16;
        #pragma unroll
        for (int sub = 0; sub < 2; sub++){
            long k0 = kbase + sub * 32;
            const __half* ap = Ab + (long)r0 * a.lda + k0 + ch * 8;
            cpa16(dst0 + sub * 16384,        ap);
            cpa16(dst0 + sub * 16384 + 4096, ap + 64 * a.lda);
            const __half* bp = Bb + (long)r0 * a.ldb + k0 + ch * 8;
            cpa16(dst0 + sub * 16384 + 8192,        bp);
            cpa16(dst0 + sub * 16384 + 8192 + 4096, bp + 64 * a.ldb);
        }
    };

    const int aRow = wm * 64 + (lane & 15);
    const uint32_t lqA = (uint32_t)(((lane & 15) >> 1) & 3);
    const uint32_t aC0 = (uint32_t)(lane >> 4);
    const int bRow = wn * 32 + (lane & 7) + ((lane >> 4) & 1) * 8;
    const uint32_t lqB = (uint32_t)(((lane & 7) >> 1) & 3);
    const uint32_t bC0 = (uint32_t)((lane >> 3) & 1);

    issue(0); CP_COMMIT();
    issue(1); CP_COMMIT();

    for (int i = 0; i < NS; i++){
        CP_WAIT1();
        __syncthreads();
        issue(i + 2);
        CP_COMMIT();

        const uint32_t stb = sbase + (uint32_t)(i % 3) * STG64;
        #pragma unroll
        for (int sub = 0; sub < 2; sub++){
            const uint32_t sb = stb + (uint32_t)sub * 16384u;
            #pragma unroll
            for (int ks = 0; ks < 2; ks++){
                const uint32_t qa = ((aC0 + 2 * ks) ^ lqA) * 16u;
                const uint32_t qb = ((bC0 + 2 * ks) ^ lqB) * 16u;
                uint32_t Afh[4][4], Bfh[2][4];
                #pragma unroll
                for (int mi = 0; mi < 4; mi++){
                    uint32_t ad = sb + (uint32_t)(aRow + mi * 16) * 64u + qa;
                    LDSM4(Afh[mi], ad);
                }
                #pragma unroll
                for (int nb = 0; nb < 2; nb++){
                    uint32_t bd = sb + 8192u + (uint32_t)(bRow + nb * 16) * 64u + qb;
                    LDSM4(Bfh[nb], bd);
                }
                #pragma unroll
                for (int mi = 0; mi < 4; mi++)
                    #pragma unroll
                    for (int ni = 0; ni < 4; ni++){
                        int nb = ni >> 1, h = (ni & 1) * 2;
                        MMA16816(acc[mi][ni], Afh[mi], Bfh[nb][h], Bfh[nb][h + 1]);
                    }
            }
        }
    }
}

// ---- fused psi_v (EPI8) + psi_l (EPI9) kernel -----------------------------
__global__ void __launch_bounds__(256, 2) mma_psi_fused(GPair P)
{
    extern __shared__ __align__(128) char smem[];
    const int half = blockIdx.x >> 5;
    const int idx  = blockIdx.x & 31;
    const int b = blockIdx.z;
    GArgs a = half ? P.g1 : P.g0;
    int bx, by;
    if (!half){ bx = idx & 15; by = idx >> 4; }   // psi_v: x=16, y=2
    else      { bx = idx & 1;  by = idx >> 1; }   // psi_l: x=2,  y=16
    const int bn0 = bx << 7, bm0 = by << 7;

    float acc[4][4][4];
    #pragma unroll
    for (int i = 0; i < 4; i++)
        #pragma unroll
        for (int j = 0; j < 4; j++)
            #pragma unroll
            for (int t = 0; t < 4; t++) acc[i][j][t] = 0.0f;

    gemm_main<1>(a, smem, bn0, bm0, b, acc);

    const int lane = threadIdx.x & 31, w = threadIdx.x >> 5;
    const int wm = w >> 2, wn = w & 3;
    const int r1 = lane >> 2, cq = (lane & 3) * 2;
    __half* Ch = (__half*)a.C;
    const long cb = (long)b * a.sC;
    #pragma unroll
    for (int mi = 0; mi < 4; mi++){
        int m0 = bm0 + wm * 64 + mi * 16 + r1;
        float s0 = 0.f, b0_ = 0.f, s1 = 0.f, b1_ = 0.f;
        if (!half){
            s0 = a.gs[m0] * BN_RS;     b0_ = a.bs[m0];
            s1 = a.gs[m0 + 8] * BN_RS; b1_ = a.bs[m0 + 8];
        }
        #pragma unroll
        for (int ni = 0; ni < 4; ni++){
            int n = bn0 + wn * 32 + ni * 8 + cq;
            float v0 = acc[mi][ni][0], v1 = acc[mi][ni][1];
            float v2 = acc[mi][ni][2], v3 = acc[mi][ni][3];
            if (!half){  // row BN
                v0 = fmaxf(fmaf(v0, s0, b0_), 0.f); v1 = fmaxf(fmaf(v1, s0, b0_), 0.f);
                v2 = fmaxf(fmaf(v2, s1, b1_), 0.f); v3 = fmaxf(fmaf(v3, s1, b1_), 0.f);
            } else {     // col BN
                float gs0 = a.gs[n] * BN_RS, bb0 = a.bs[n];
                float gs1 = a.gs[n + 1] * BN_RS, bb1 = a.bs[n + 1];
                v0 = fmaxf(fmaf(v0, gs0, bb0), 0.f); v1 = fmaxf(fmaf(v1, gs1, bb1), 0.f);
                v2 = fmaxf(fmaf(v2, gs0, bb0), 0.f); v3 = fmaxf(fmaf(v3, gs1, bb1), 0.f);
            }
            *(uint32_t*)(Ch + cb + (long)m0 * a.ldc + n)       = packh(v0, v1);
            *(uint32_t*)(Ch + cb + (long)(m0 + 8) * a.ldc + n) = packh(v2, v3);
        }
    }
}

// ---- standalone GEMM (EPI: 0 fp32, 7 fp16) --------------------------------
template<int EPI, int NP>
__global__ void __launch_bounds__(256, 2) mma_gemm(GArgs a)
{
    extern __shared__ __align__(128) char smem[];
    const int bn0 = blockIdx.x << 7, bm0 = blockIdx.y << 7, b = blockIdx.z;

    float acc[4][4][4];
    #pragma unroll
    for (int i = 0; i < 4; i++)
        #pragma unroll
        for (int j = 0; j < 4; j++)
            #pragma unroll
            for (int t = 0; t < 4; t++) acc[i][j][t] = 0.0f;

    gemm_main<NP>(a, smem, bn0, bm0, b, acc);

    const int lane = threadIdx.x & 31, w = threadIdx.x >> 5;
    const int wm = w >> 2, wn = w & 3;
    const int r1 = lane >> 2, cq = (lane & 3) * 2;
    if (EPI == 7){
        __half* Ch = (__half*)a.C;
        const long cb = (long)b * a.sC;
        #pragma unroll
        for (int mi = 0; mi < 4; mi++){
            int m0 = bm0 + wm * 64 + mi * 16 + r1;
            #pragma unroll
            for (int ni = 0; ni < 4; ni++){
                int n = bn0 + wn * 32 + ni * 8 + cq;
                *(uint32_t*)(Ch + cb + (long)m0 * a.ldc + n)
                    = packh(acc[mi][ni][0], acc[mi][ni][1]);
                *(uint32_t*)(Ch + cb + (long)(m0 + 8) * a.ldc + n)
                    = packh(acc[mi][ni][2], acc[mi][ni][3]);
            }
        }
    } else {
        float* Cb = (float*)a.C + (long)b * a.sC;
        #pragma unroll
        for (int mi = 0; mi < 4; mi++){
            int m0 = bm0 + wm * 64 + mi * 16 + r1;
            #pragma unroll
            for (int ni = 0; ni < 4; ni++){
                int n = bn0 + wn * 32 + ni * 8 + cq;
                *(float2*)(Cb + (long)m0 * a.ldc + n)
                    = make_float2(acc[mi][ni][0], acc[mi][ni][1]);
                *(float2*)(Cb + (long)(m0 + 8) * a.ldc + n)
                    = make_float2(acc[mi][ni][2], acc[mi][ni][3]);
            }
        }
    }
}

// ---------------- reductions ----------------
__device__ __forceinline__ float warpSum(float v){
    #pragma unroll
    for (int o = 16; o; o >>= 1) v += __shfl_xor_sync(0xffffffffu, v, o);
    return v;
}
__device__ __forceinline__ float warpMax(float v){
    #pragma unroll
    for (int o = 16; o; o >>= 1) v = fmaxf(v, __shfl_xor_sync(0xffffffffu, v, o));
    return v;
}
__device__ __forceinline__ float blockSum(float v){
    __shared__ float sh[32];
    int w = threadIdx.x >> 5, l = threadIdx.x & 31;
    v = warpSum(v);
    if (l == 0) sh[w] = v;
    __syncthreads();
    int nw = blockDim.x >> 5;
    if (w == 0){ float x = (l < nw) ? sh[l] : 0.0f; x = warpSum(x); if (l == 0) sh[0] = x; }
    __syncthreads();
    float r = sh[0];
    __syncthreads();
    return r;
}
__device__ __forceinline__ float blockMax(float v){
    __shared__ float sh[32];
    int w = threadIdx.x >> 5, l = threadIdx.x & 31;
    v = warpMax(v);
    if (l == 0) sh[w] = v;
    __syncthreads();
    int nw = blockDim.x >> 5;
    if (w == 0){ float x = (l < nw) ? sh[l] : -INFINITY; x = warpMax(x); if (l == 0) sh[0] = x; }
    __syncthreads();
    float r = sh[0];
    __syncthreads();
    return r;
}

// ---------------- elementwise kernels ----------------
// one launch: split v2l, l2v, wv, wl (hi only)
__global__ void __launch_bounds__(256)
k_split_all(const float4* __restrict__ v2l, uint2* __restrict__ v2lh,
            const float4* __restrict__ l2v, uint2* __restrict__ l2vh,
            const float4* __restrict__ wv, uint2* __restrict__ wvh,
            const float4* __restrict__ wl, uint2* __restrict__ wlh,
            int nBig, int nW)
{
    long i = (long)blockIdx.x * blockDim.x + threadIdx.x;
    long stride = (long)gridDim.x * blockDim.x;
    long total = 2L * nBig + 2L * nW;
    for (; i < total; i += stride){
        const float4* in; uint2* hi; long j;
        if (i < nBig){ in = v2l; hi = v2lh; j = i; }
        else if (i < 2L * nBig){ in = l2v; hi = l2vh; j = i - nBig; }
        else if (i < 2L * nBig + nW){ in = wv; hi = wvh; j = i - 2L * nBig; }
        else { in = wl; hi = wlh; j = i - 2L * nBig - nW; }
        uint2 h;
        split16h(in[j], h);
        hi[j] = h;
    }
}

// fused norms: blocks [0,4096): Yv rows (C=2048); [4096, 36864): Zl rows (D=256)
__global__ void __launch_bounds__(256)
k_norms(const uint2* __restrict__ Y, uint32_t* __restrict__ Eh, uint32_t* __restrict__ Oh,
        const uint32_t* __restrict__ Z, uint32_t* __restrict__ Zh)
{
    int t = threadIdx.x;
    if (blockIdx.x < BATCH * DD){
        long row = blockIdx.x;
        const uint2* y = Y + row * 512;
        uint2 u0 = y[t], u1 = y[t + 256];
        float2 a0 = __half22float2(*(__half2*)&u0.x);
        float2 a1 = __half22float2(*(__half2*)&u0.y);
        float2 a2 = __half22float2(*(__half2*)&u1.x);
        float2 a3 = __half22float2(*(__half2*)&u1.y);
        float s = a0.x*a0.x + a0.y*a0.y + a1.x*a1.x + a1.y*a1.y
                + a2.x*a2.x + a2.y*a2.y + a3.x*a3.x + a3.y*a3.y;
        s = blockSum(s);
        float inv = 1.0f / fmaxf(sqrtf(s), 1e-12f);
        long eb = row * 512;
        Eh[eb + t]       = packh(a0.x * inv, a1.x * inv);
        Oh[eb + t]       = packh(a0.y * inv, a1.y * inv);
        Eh[eb + t + 256] = packh(a2.x * inv, a3.x * inv);
        Oh[eb + t + 256] = packh(a2.y * inv, a3.y * inv);
    } else {
        long row = blockIdx.x - BATCH * DD;
        float2 v = make_float2(0.f, 0.f);
        uint32_t u = 0;
        if (t < 128){
            u = Z[row * 128 + t];
            v = __half22float2(*(__half2*)&u);
        }
        float s = blockSum(v.x * v.x + v.y * v.y);
        if (t < 128){
            float inv = 1.0f / fmaxf(sqrtf(s), 1e-12f);
            Zh[row * 128 + t] = packh(v.x * inv, v.y * inv);
        }
    }
}

// transpose lat hi [b,256,1024] -> latT hi [b,1024,256]
__global__ void __launch_bounds__(256)
k_transpose(const uint32_t* __restrict__ sH, uint32_t* __restrict__ dH)
{
    __shared__ unsigned short tile[32][34];
    const int b = blockIdx.z, h0 = blockIdx.x * 32, d0 = blockIdx.y * 32;
    const int t = threadIdx.x;
    #pragma unroll
    for (int i = 0; i < 2; i++){
        int s = t + i * 256;
        int d = s >> 4, hu = s & 15;
        uint32_t v = sH[(long)(b * 256 + d0 + d) * 512 + (h0 >> 1) + hu];
        tile[d][2 * hu]     = (unsigned short)(v & 0xFFFFu);
        tile[d][2 * hu + 1] = (unsigned short)(v >> 16);
    }
    __syncthreads();
    #pragma unroll
    for (int i = 0; i < 2; i++){
        int s = t + i * 256;
        int h = s >> 4, du = s & 15;
        uint32_t v = (uint32_t)tile[2 * du][h] | ((uint32_t)tile[2 * du + 1][h] << 16);
        dH[(long)(b * 1024 + h0 + h) * 128 + (d0 >> 1) + du] = v;
    }
}

// latent row inverse norms from fp16 hi
__global__ void __launch_bounds__(256)
k_latnorm(const uint32_t* __restrict__ H, float* __restrict__ R)
{
    long row = blockIdx.x;
    long base = row * 512;
    int t = threadIdx.x;
    float s = 0.0f;
    #pragma unroll
    for (int i = 0; i < 2; i++){
        uint32_t uh = H[base + t + i * 256];
        float2 fh = __half22float2(*(__half2*)&uh);
        s += fh.x * fh.x + fh.y * fh.y;
    }
    s = blockSum(s);
    if (t == 0) R[row] = 1.0f / fmaxf(sqrtf(s), 1e-12f);
}

__global__ void __launch_bounds__(256)
k_softmax(const float* __restrict__ G, const float* __restrict__ R,
          uint32_t* __restrict__ Gh)
{
    long row = blockIdx.x;
    long bb = row >> 8;
    int t = threadIdx.x;
    float ri = R[row];
    float re = R[(bb << 8) + t];
    float x = G[row * 256 + t] * ri * re;
    float mx = blockMax(x);
    float p = expf(x - mx);
    float sm = blockSum(p);
    float g = p / sm;
    float gn = __shfl_down_sync(0xffffffffu, g, 1);
    if ((t & 1) == 0){
        Gh[row * 128 + (t >> 1)] = packh(g, gn);
    }
}

// ---------------- launch ----------------
extern "C" void kernel_launch(void* const* d_in, const int* in_sizes, int n_in,
                              void* d_out, int out_size)
{
    const float* v2l = (const float*)d_in[0];
    const float* l2v = (const float*)d_in[1];
    const float* wv  = (const float*)d_in[2];
    const float* gv  = (const float*)d_in[3];
    const float* bv  = (const float*)d_in[4];
    const float* wl  = (const float*)d_in[5];
    const float* gl  = (const float*)d_in[6];
    const float* bl  = (const float*)d_in[7];
    float* out = (float*)d_out;

    float *G, *invr;
    __half *v2lh, *l2vh, *wvh, *wlh, *Yvh, *Zlh;
    __half *Eh, *Oh, *Zh, *lath, *latTh, *Ghb, *l2Th;
    cudaGetSymbolAddress((void**)&G, d_G);
    cudaGetSymbolAddress((void**)&invr, d_invr);
    cudaGetSymbolAddress((void**)&v2lh, g_v2lh);
    cudaGetSymbolAddress((void**)&l2vh, g_l2vh);
    cudaGetSymbolAddress((void**)&wvh, g_wvh);
    cudaGetSymbolAddress((void**)&wlh, g_wlh);
    cudaGetSymbolAddress((void**)&Yvh, g_Yvh);
    cudaGetSymbolAddress((void**)&Zlh, g_Zlh);
    cudaGetSymbolAddress((void**)&Eh, g_Eh);
    cudaGetSymbolAddress((void**)&Oh, g_Oh);
    cudaGetSymbolAddress((void**)&Zh, g_Zh);
    cudaGetSymbolAddress((void**)&lath, g_lath);
    cudaGetSymbolAddress((void**)&latTh, g_latTh);
    cudaGetSymbolAddress((void**)&Ghb, g_Gh);
    cudaGetSymbolAddress((void**)&l2Th, g_l2Th);

    cudaFuncSetAttribute(mma_psi_fused, cudaFuncAttributeMaxDynamicSharedMemorySize, G_SMEM);
    cudaFuncSetAttribute(mma_gemm<7,2>, cudaFuncAttributeMaxDynamicSharedMemorySize, G_SMEM);
    cudaFuncSetAttribute(mma_gemm<0,1>, cudaFuncAttributeMaxDynamicSharedMemorySize, G_SMEM);
    cudaFuncSetAttribute(mma_gemm<7,1>, cudaFuncAttributeMaxDynamicSharedMemorySize, G_SMEM);

    const long FEAT = (long)CCH * HWD;
    dim3 blk(256);

    // 0) all splits, one launch
    k_split_all<<<16896, blk>>>((const float4*)v2l, (uint2*)v2lh,
                                (const float4*)l2v, (uint2*)l2vh,
                                (const float4*)wv, (uint2*)wvh,
                                (const float4*)wl, (uint2*)wlh,
                                (int)(BATCH*FEAT/4), DD*HWD/4);

    // 1+2) fused psi_v + psi_l
    {
        GPair P;
        P.g0 = { wvh, v2lh, nullptr, nullptr, Yvh, gv, bv,
                 0, FEAT, (long)DD*CCH, HWD, HWD, CCH, HWD };
        P.g1 = { l2vh, wlh, nullptr, nullptr, Zlh, gl, bl,
                 FEAT, 0, (long)CCH*DD, HWD, HWD, DD, HWD };
        mma_psi_fused<<<dim3(64, 1, BATCH), blk, G_SMEM>>>(P);
    }
    // 3+4) fused norms
    k_norms<<<BATCH*DD + BATCH*CCH, blk>>>((const uint2*)Yvh, (uint32_t*)Eh, (uint32_t*)Oh,
                                           (const uint32_t*)Zlh, (uint32_t*)Zh);
    // 5) lat = E.Vlow^T + O.Vhigh^T -> fp16 hi
    {
        GArgs a = { Eh, v2lh, Oh, v2lh + (long)HWD*HWD,
                    lath, nullptr, nullptr,
                    (long)DD*HWD, FEAT, (long)DD*HWD, HWD, HWD, HWD, HWD };
        mma_gemm<7,2><<<dim3(HWD/128, DD/128, BATCH), blk, G_SMEM>>>(a);
    }
    // 6) transpose lat hi -> latT hi
    k_transpose<<<dim3(32, 8, BATCH), blk>>>((const uint32_t*)lath, (uint32_t*)latTh);
    // 7) latent row inverse norms
    k_latnorm<<<BATCH*DD, blk>>>((const uint32_t*)lath, invr);
    // 8) G = lat . lat^T (fp32)
    {
        GArgs a = { lath, lath, nullptr, nullptr,
                    G, nullptr, nullptr,
                    (long)DD*HWD, (long)DD*HWD, (long)DD*DD, HWD, HWD, DD, HWD };
        mma_gemm<0,1><<<dim3(DD/128, DD/128, BATCH), blk, G_SMEM>>>(a);
    }
    // 9) aff = softmax(G * invr_d * invr_e) -> fp16 hi
    k_softmax<<<BATCH*DD, blk>>>(G, invr, (uint32_t*)Ghb);
    // 10) l2T = latT . aff^T -> fp16 hi
    {
        GArgs a = { latTh, Ghb, nullptr, nullptr,
                    l2Th, nullptr, nullptr,
                    (long)HWD*DD, (long)DD*DD, (long)HWD*DD, DD, DD, DD, DD };
        mma_gemm<7,1><<<dim3(DD/128, HWD/128, BATCH), blk, G_SMEM>>>(a);
    }
    // 11) out = Zl_adj . l2T^T (fp32)
    {
        GArgs a = { Zh, l2Th, nullptr, nullptr,
                    out, nullptr, nullptr,
                    (long)CCH*DD, (long)HWD*DD, (long)CCH*HWD, DD, DD, HWD, DD };
        mma_gemm<0,1><<<dim3(HWD/128, CCH/128, BATCH), blk, G_SMEM>>>(a);
    }
}